// round 1
// baseline (speedup 1.0000x reference)
#include <cuda_runtime.h>
#include <cuda_bf16.h>

#define HH 2
#define BB 2048
#define MM 64
#define DD 16
#define NREL 32

__global__ void __launch_bounds__(128) ripple_kernel(
    const int* __restrict__ items,
    const int* __restrict__ heads,
    const int* __restrict__ rels,
    const int* __restrict__ tails,
    const float* __restrict__ ent,
    const float* __restrict__ relm,
    float* __restrict__ out)
{
    __shared__ float s_item[DD];
    __shared__ float s_q[NREL * DD];   // q[r][j] = sum_i item[i] * R[r][i][j]
    __shared__ float s_wmax[4];
    __shared__ float s_wsum[4];
    __shared__ float s_red[4][DD];

    const int b    = blockIdx.x;
    const int tid  = threadIdx.x;      // 0..127
    const int w    = tid >> 5;         // warp 0..3
    const int lane = tid & 31;

    // ---- item embedding into shared ----
    if (tid < DD) {
        int item = items[b];
        s_item[tid] = ent[(long)item * DD + tid];
    }
    __syncthreads();

    // ---- precompute q[r][j] for all 32 relations (512 entries, 4/thread) ----
    #pragma unroll
    for (int e = 0; e < 4; e++) {
        int idx = e * 128 + tid;             // 0..511
        int r = idx >> 4;
        int j = idx & 15;
        const float* Rp = relm + r * (DD * DD) + j;
        float acc = 0.f;
        #pragma unroll
        for (int i = 0; i < DD; i++)
            acc = fmaf(s_item[i], Rp[i * DD], acc);
        s_q[idx] = acc;
    }
    __syncthreads();

    // ---- each thread owns one (h, m) memory slot ----
    const int h = tid >> 6;
    const int m = tid & 63;
    const int base = (h * BB + b) * MM + m;   // [H, B, M] layout
    const int hidx = heads[base];
    const int ridx = rels[base];
    const int tidx = tails[base];

    // logit = head · q[rel]
    const float4* hv = (const float4*)(ent + (long)hidx * DD);
    float4 a0 = hv[0], a1 = hv[1], a2 = hv[2], a3 = hv[3];
    const float* q = s_q + ridx * DD;
    float lg =
        a0.x*q[0]  + a0.y*q[1]  + a0.z*q[2]  + a0.w*q[3]  +
        a1.x*q[4]  + a1.y*q[5]  + a1.z*q[6]  + a1.w*q[7]  +
        a2.x*q[8]  + a2.y*q[9]  + a2.z*q[10] + a2.w*q[11] +
        a3.x*q[12] + a3.y*q[13] + a3.z*q[14] + a3.w*q[15];

    // ---- softmax over m (64 slots = warp pair {2h, 2h+1}) ----
    float mx = lg;
    #pragma unroll
    for (int o = 16; o; o >>= 1) mx = fmaxf(mx, __shfl_xor_sync(0xffffffffu, mx, o));
    if (lane == 0) s_wmax[w] = mx;
    __syncthreads();
    const int pw = w & 2;                      // 0 for h=0, 2 for h=1
    float gmax = fmaxf(s_wmax[pw], s_wmax[pw + 1]);
    float ex = __expf(lg - gmax);
    float sm = ex;
    #pragma unroll
    for (int o = 16; o; o >>= 1) sm += __shfl_xor_sync(0xffffffffu, sm, o);
    if (lane == 0) s_wsum[w] = sm;
    __syncthreads();
    float pi = ex / (s_wsum[pw] + s_wsum[pw + 1]);

    // ---- weighted tail aggregation across ALL 128 slots (both hops) ----
    const float4* tv = (const float4*)(ent + (long)tidx * DD);
    float4 t0 = tv[0], t1 = tv[1], t2 = tv[2], t3 = tv[3];
    float v[DD] = {
        t0.x*pi, t0.y*pi, t0.z*pi, t0.w*pi,
        t1.x*pi, t1.y*pi, t1.z*pi, t1.w*pi,
        t2.x*pi, t2.y*pi, t2.z*pi, t2.w*pi,
        t3.x*pi, t3.y*pi, t3.z*pi, t3.w*pi };
    #pragma unroll
    for (int o = 16; o; o >>= 1) {
        #pragma unroll
        for (int d = 0; d < DD; d++)
            v[d] += __shfl_xor_sync(0xffffffffu, v[d], o);
    }
    if (lane == 0) {
        #pragma unroll
        for (int d = 0; d < DD; d++) s_red[w][d] = v[d];
    }
    __syncthreads();

    // ---- final dot with item + sigmoid ----
    if (tid < DD) {
        float u = s_red[0][tid] + s_red[1][tid] + s_red[2][tid] + s_red[3][tid];
        float p = u * s_item[tid];
        #pragma unroll
        for (int o = 8; o; o >>= 1) p += __shfl_xor_sync(0x0000ffffu, p, o);
        if (tid == 0) out[b] = 1.f / (1.f + __expf(-p));
    }
}

extern "C" void kernel_launch(void* const* d_in, const int* in_sizes, int n_in,
                              void* d_out, int out_size) {
    ripple_kernel<<<BB, 128>>>(
        (const int*)d_in[0],     // items   [B]
        (const int*)d_in[1],     // heads   [H,B,M]
        (const int*)d_in[2],     // relations [H,B,M]
        (const int*)d_in[3],     // tails   [H,B,M]
        (const float*)d_in[4],   // ent_emb [N_ENT, D]
        (const float*)d_in[5],   // rel_emb [N_REL, D, D]
        (float*)d_out);          // predicts [B]
}

// round 5
// speedup vs baseline: 1.1825x; 1.1825x over previous
#include <cuda_runtime.h>
#include <cuda_bf16.h>

#define HH 2
#define BB 2048
#define MM 64
#define DD 16
#define NREL 32

__global__ void __launch_bounds__(128) ripple_kernel(
    const int* __restrict__ items,
    const int* __restrict__ heads,
    const int* __restrict__ rels,
    const int* __restrict__ tails,
    const float* __restrict__ ent,
    const float* __restrict__ relm,
    float* __restrict__ out)
{
    __shared__ float s_item[DD];
    __shared__ float s_q[NREL * DD];   // q[r][j] = sum_i item[i] * R[r][i][j]
    __shared__ float s_wmax[4];
    __shared__ float s_wsum[4];
    __shared__ float s_red[4];

    const int b    = blockIdx.x;
    const int tid  = threadIdx.x;      // 0..127, one (h,m) slot each
    const int w    = tid >> 5;         // warp 0..3
    const int lane = tid & 31;

    // ---- kick off index loads + row gathers IMMEDIATELY (hide 2-level miss chain) ----
    const int base = ((tid >> 6) * BB + b) * MM + (tid & 63);   // [H,B,M]
    const int hidx = heads[base];
    const int ridx = rels[base];
    const int tidx = tails[base];

    const float4* hv = (const float4*)(ent + (long)hidx * DD);
    const float4* tv = (const float4*)(ent + (long)tidx * DD);
    float4 a0 = hv[0], a1 = hv[1], a2 = hv[2], a3 = hv[3];   // head row
    float4 t0 = tv[0], t1 = tv[1], t2 = tv[2], t3 = tv[3];   // tail row

    if (tid < DD) {
        int item = items[b];
        s_item[tid] = ent[(long)item * DD + tid];
    }
    __syncthreads();

    // ---- tail · item (frees tail registers before q loop) ----
    float ts =
        t0.x*s_item[0]  + t0.y*s_item[1]  + t0.z*s_item[2]  + t0.w*s_item[3]  +
        t1.x*s_item[4]  + t1.y*s_item[5]  + t1.z*s_item[6]  + t1.w*s_item[7]  +
        t2.x*s_item[8]  + t2.y*s_item[9]  + t2.z*s_item[10] + t2.w*s_item[11] +
        t3.x*s_item[12] + t3.y*s_item[13] + t3.z*s_item[14] + t3.w*s_item[15];

    // ---- q[r][j] = item^T R[r], one float4 of q per thread (16 LDG.128) ----
    {
        const int r  = tid >> 2;        // 0..31
        const int j4 = tid & 3;         // which float4 of the 16-wide row
        const float4* R4 = (const float4*)relm + r * (DD * 4) + j4;
        float4 acc = make_float4(0.f, 0.f, 0.f, 0.f);
        #pragma unroll
        for (int i = 0; i < DD; i++) {
            float it = s_item[i];
            float4 rv = R4[i * 4];
            acc.x = fmaf(it, rv.x, acc.x);
            acc.y = fmaf(it, rv.y, acc.y);
            acc.z = fmaf(it, rv.z, acc.z);
            acc.w = fmaf(it, rv.w, acc.w);
        }
        ((float4*)s_q)[tid] = acc;
    }
    __syncthreads();

    // ---- logit = head · q[rel] ----
    const float4* q4 = (const float4*)(s_q + ridx * DD);
    float4 q0 = q4[0], q1 = q4[1], q2 = q4[2], q3 = q4[3];
    float lg =
        a0.x*q0.x + a0.y*q0.y + a0.z*q0.z + a0.w*q0.w +
        a1.x*q1.x + a1.y*q1.y + a1.z*q1.z + a1.w*q1.w +
        a2.x*q2.x + a2.y*q2.y + a2.z*q2.z + a2.w*q2.w +
        a3.x*q3.x + a3.y*q3.y + a3.z*q3.z + a3.w*q3.w;

    // ---- softmax over the 64 slots of this hop (warp pair {2h, 2h+1}) ----
    float mx = lg;
    #pragma unroll
    for (int o = 16; o; o >>= 1) mx = fmaxf(mx, __shfl_xor_sync(0xffffffffu, mx, o));
    if (lane == 0) s_wmax[w] = mx;
    __syncthreads();
    const int pw = w & 2;
    float gmax = fmaxf(s_wmax[pw], s_wmax[pw + 1]);
    float ex = __expf(lg - gmax);
    float sm = ex;
    #pragma unroll
    for (int o = 16; o; o >>= 1) sm += __shfl_xor_sync(0xffffffffu, sm, o);
    if (lane == 0) s_wsum[w] = sm;
    __syncthreads();
    float pi = ex / (s_wsum[pw] + s_wsum[pw + 1]);

    // ---- scalar contribution: pi * (tail · item); block-reduce over 128 slots ----
    float p = pi * ts;
    #pragma unroll
    for (int o = 16; o; o >>= 1) p += __shfl_xor_sync(0xffffffffu, p, o);
    if (lane == 0) s_red[w] = p;
    __syncthreads();

    if (tid == 0) {
        float tot = s_red[0] + s_red[1] + s_red[2] + s_red[3];
        out[b] = 1.f / (1.f + __expf(-tot));
    }
}

extern "C" void kernel_launch(void* const* d_in, const int* in_sizes, int n_in,
                              void* d_out, int out_size) {
    ripple_kernel<<<BB, 128>>>(
        (const int*)d_in[0],     // items     [B]
        (const int*)d_in[1],     // heads     [H,B,M]
        (const int*)d_in[2],     // relations [H,B,M]
        (const int*)d_in[3],     // tails     [H,B,M]
        (const float*)d_in[4],   // ent_emb   [N_ENT, D]
        (const float*)d_in[5],   // rel_emb   [N_REL, D, D]
        (float*)d_out);          // predicts  [B]
}

// round 6
// speedup vs baseline: 1.5967x; 1.3503x over previous
#include <cuda_runtime.h>
#include <cuda_bf16.h>

#define HH 2
#define BB 2048
#define MM 64
#define DD 16
#define NREL 32
#define FULLM 0xffffffffu

__global__ void __launch_bounds__(128) ripple_kernel(
    const int* __restrict__ items,
    const int* __restrict__ heads,
    const int* __restrict__ rels,
    const int* __restrict__ tails,
    const float* __restrict__ ent,
    const float* __restrict__ relm,
    float* __restrict__ out)
{
    __shared__ float s_item[DD];
    __shared__ float s_q[NREL * DD];   // q[r][j] = sum_i item[i] * R[r][i][j]
    __shared__ float s_wmax[4];
    __shared__ float s_wsum[4];
    __shared__ float s_red[4];

    const int b    = blockIdx.x;
    const int tid  = threadIdx.x;      // 128 threads
    const int w    = tid >> 5;         // warp 0..3 ; warp handles slots [32w, 32w+32)
    const int lane = tid & 31;
    const int a    = lane >> 2;        // quad index 0..7
    const int bq   = lane & 3;         // quarter within row 0..3

    // hop of this warp's slots: slots 32w..32w+31 all lie in hop h = w>>1
    const int h = w >> 1;
    // index base for round k, quad a:  slot_blk = 32w + 8k + a  →  m = (w&1)*32 + 8k + a
    const int ibase = (h * BB + b) * MM + (w & 1) * 32 + a;   // + 8k per round

    // ---- load round indices up front (independent of item; overlaps q-compute) ----
    int hix[4], rix[4], tix[4];
    #pragma unroll
    for (int k = 0; k < 4; k++) {
        hix[k] = heads[ibase + 8 * k];
        rix[k] = rels [ibase + 8 * k];
        tix[k] = tails[ibase + 8 * k];
    }

    // ---- item embedding into shared ----
    if (tid < DD) s_item[tid] = ent[(long)items[b] * DD + tid];
    __syncthreads();

    // ---- q[r][j] = item^T R[r]; one float4 of q per thread ----
    {
        const int r  = tid >> 2;
        const int j4 = tid & 3;
        const float4* R4 = (const float4*)relm + r * (DD * 4) + j4;
        float4 acc = make_float4(0.f, 0.f, 0.f, 0.f);
        #pragma unroll
        for (int i = 0; i < DD; i++) {
            float it = s_item[i];
            float4 rv = R4[i * 4];
            acc.x = fmaf(it, rv.x, acc.x);
            acc.y = fmaf(it, rv.y, acc.y);
            acc.z = fmaf(it, rv.z, acc.z);
            acc.w = fmaf(it, rv.w, acc.w);
        }
        ((float4*)s_q)[tid] = acc;
    }

    // item quarter for this lane (constant across rounds)
    const float4 itq = ((const float4*)s_item)[bq];
    __syncthreads();

    // ---- cooperative gather rounds: quad (4 lanes) fetches one slot's 64B row ----
    float ph[4], pt[4];
    #pragma unroll
    for (int k = 0; k < 4; k++) {
        // head/tail row quarter: 4 lanes cover 64B contiguously → 8 lines per warp-LDG
        const float4 hv = ((const float4*)(ent + (long)hix[k] * DD))[bq];
        const float4 tv = ((const float4*)(ent + (long)tix[k] * DD))[bq];
        const float4 qv = ((const float4*)(s_q + rix[k] * DD))[bq];
        ph[k] = hv.x * qv.x  + hv.y * qv.y  + hv.z * qv.z  + hv.w * qv.w;
        pt[k] = tv.x * itq.x + tv.y * itq.y + tv.z * itq.z + tv.w * itq.w;
    }
    // quad reduce: sum over the 4 quarters (lanes differing in bits 0,1)
    #pragma unroll
    for (int k = 0; k < 4; k++) {
        ph[k] += __shfl_xor_sync(FULLM, ph[k], 1);
        ph[k] += __shfl_xor_sync(FULLM, ph[k], 2);
        pt[k] += __shfl_xor_sync(FULLM, pt[k], 1);
        pt[k] += __shfl_xor_sync(FULLM, pt[k], 2);
    }
    // thread's own slot: s_loc = 8*bq + a  →  take round k = bq
    float lg = (bq == 0) ? ph[0] : (bq == 1) ? ph[1] : (bq == 2) ? ph[2] : ph[3];
    float ts = (bq == 0) ? pt[0] : (bq == 1) ? pt[1] : (bq == 2) ? pt[2] : pt[3];

    // ---- softmax over the 64 slots of this hop (warp pair {2h, 2h+1}) ----
    float mx = lg;
    #pragma unroll
    for (int o = 16; o; o >>= 1) mx = fmaxf(mx, __shfl_xor_sync(FULLM, mx, o));
    if (lane == 0) s_wmax[w] = mx;
    __syncthreads();
    const int pw = w & 2;
    float gmax = fmaxf(s_wmax[pw], s_wmax[pw + 1]);
    float ex = __expf(lg - gmax);
    float sm = ex;
    #pragma unroll
    for (int o = 16; o; o >>= 1) sm += __shfl_xor_sync(FULLM, sm, o);
    if (lane == 0) s_wsum[w] = sm;
    __syncthreads();
    float pi = ex / (s_wsum[pw] + s_wsum[pw + 1]);

    // ---- scalar contribution pi*(tail·item); block reduce over 128 slots ----
    float p = pi * ts;
    #pragma unroll
    for (int o = 16; o; o >>= 1) p += __shfl_xor_sync(FULLM, p, o);
    if (lane == 0) s_red[w] = p;
    __syncthreads();

    if (tid == 0) {
        float tot = s_red[0] + s_red[1] + s_red[2] + s_red[3];
        out[b] = 1.f / (1.f + __expf(-tot));
    }
}

extern "C" void kernel_launch(void* const* d_in, const int* in_sizes, int n_in,
                              void* d_out, int out_size) {
    ripple_kernel<<<BB, 128>>>(
        (const int*)d_in[0],     // items     [B]
        (const int*)d_in[1],     // heads     [H,B,M]
        (const int*)d_in[2],     // relations [H,B,M]
        (const int*)d_in[3],     // tails     [H,B,M]
        (const float*)d_in[4],   // ent_emb   [N_ENT, D]
        (const float*)d_in[5],   // rel_emb   [N_REL, D, D]
        (float*)d_out);          // predicts  [B]
}

// round 7
// speedup vs baseline: 1.6681x; 1.0447x over previous
#include <cuda_runtime.h>
#include <cuda_bf16.h>

#define HH 2
#define BB 2048
#define MM 64
#define DD 16
#define NREL 32
#define FULLM 0xffffffffu

// q[b][r][j] = sum_i item_e[b][i] * R[r][i][j]   -> [B, NREL*DD] = 4MB scratch
__device__ float4 g_qall[BB * 128];

// ---------------- Kernel A: q precompute, 4 batches per block ----------------
__global__ void __launch_bounds__(128) q_precompute_kernel(
    const int* __restrict__ items,
    const float* __restrict__ ent,
    const float* __restrict__ relm)
{
    __shared__ float s_it[4][DD];
    const int tid = threadIdx.x;
    const int b0  = blockIdx.x * 4;

    if (tid < 4 * DD) {
        int bb = tid >> 4, d = tid & 15;
        s_it[bb][d] = ent[(long)items[b0 + bb] * DD + d];
    }
    __syncthreads();

    // thread owns (r = tid>>2, j4 = tid&3); R loaded ONCE, reused for 4 batches
    const int r  = tid >> 2;
    const int j4 = tid & 3;
    const float4* R4 = (const float4*)relm + r * (DD * 4) + j4;

    float4 acc0 = make_float4(0,0,0,0), acc1 = make_float4(0,0,0,0);
    float4 acc2 = make_float4(0,0,0,0), acc3 = make_float4(0,0,0,0);
    #pragma unroll
    for (int i = 0; i < DD; i++) {
        float4 rv = R4[i * 4];
        float i0 = s_it[0][i], i1 = s_it[1][i], i2 = s_it[2][i], i3 = s_it[3][i];
        acc0.x = fmaf(i0, rv.x, acc0.x); acc0.y = fmaf(i0, rv.y, acc0.y);
        acc0.z = fmaf(i0, rv.z, acc0.z); acc0.w = fmaf(i0, rv.w, acc0.w);
        acc1.x = fmaf(i1, rv.x, acc1.x); acc1.y = fmaf(i1, rv.y, acc1.y);
        acc1.z = fmaf(i1, rv.z, acc1.z); acc1.w = fmaf(i1, rv.w, acc1.w);
        acc2.x = fmaf(i2, rv.x, acc2.x); acc2.y = fmaf(i2, rv.y, acc2.y);
        acc2.z = fmaf(i2, rv.z, acc2.z); acc2.w = fmaf(i2, rv.w, acc2.w);
        acc3.x = fmaf(i3, rv.x, acc3.x); acc3.y = fmaf(i3, rv.y, acc3.y);
        acc3.z = fmaf(i3, rv.z, acc3.z); acc3.w = fmaf(i3, rv.w, acc3.w);
    }
    // flat float4 index within batch = r*4 + j4 = tid
    g_qall[(b0 + 0) * 128 + tid] = acc0;
    g_qall[(b0 + 1) * 128 + tid] = acc1;
    g_qall[(b0 + 2) * 128 + tid] = acc2;
    g_qall[(b0 + 3) * 128 + tid] = acc3;
}

// ---------------- Kernel B: main ----------------
__global__ void __launch_bounds__(128, 14) ripple_kernel(
    const int* __restrict__ items,
    const int* __restrict__ heads,
    const int* __restrict__ rels,
    const int* __restrict__ tails,
    const float* __restrict__ ent,
    float* __restrict__ out)
{
    __shared__ float s_item[DD];
    __shared__ float s_q[NREL * DD];
    __shared__ float s_wmax[4];
    __shared__ float s_wsum[4];
    __shared__ float s_red[4];

    const int b    = blockIdx.x;
    const int tid  = threadIdx.x;
    const int w    = tid >> 5;
    const int lane = tid & 31;
    const int a    = lane >> 2;        // quad 0..7
    const int bq   = lane & 3;         // row quarter 0..3

    const int h = w >> 1;
    const int ibase = (h * BB + b) * MM + (w & 1) * 32 + a;   // + 8k per round

    // indices up front (overlap everything)
    int hix[4], rix[4], tix[4];
    #pragma unroll
    for (int k = 0; k < 4; k++) {
        hix[k] = heads[ibase + 8 * k];
        rix[k] = rels [ibase + 8 * k];
        tix[k] = tails[ibase + 8 * k];
    }

    // q block: 2KB contiguous, 16 wavefronts
    ((float4*)s_q)[tid] = g_qall[b * 128 + tid];
    if (tid < DD) s_item[tid] = ent[(long)items[b] * DD + tid];
    __syncthreads();

    const float4 itq = ((const float4*)s_item)[bq];

    // cooperative gathers: quad fetches one slot's 64B row per round
    float ph[4], pt[4];
    #pragma unroll
    for (int k = 0; k < 4; k++) {
        const float4 hv = ((const float4*)(ent + (long)hix[k] * DD))[bq];
        const float4 tv = ((const float4*)(ent + (long)tix[k] * DD))[bq];
        const float4 qv = ((const float4*)(s_q + rix[k] * DD))[bq];
        ph[k] = hv.x * qv.x  + hv.y * qv.y  + hv.z * qv.z  + hv.w * qv.w;
        pt[k] = tv.x * itq.x + tv.y * itq.y + tv.z * itq.z + tv.w * itq.w;
    }
    #pragma unroll
    for (int k = 0; k < 4; k++) {
        ph[k] += __shfl_xor_sync(FULLM, ph[k], 1);
        ph[k] += __shfl_xor_sync(FULLM, ph[k], 2);
        pt[k] += __shfl_xor_sync(FULLM, pt[k], 1);
        pt[k] += __shfl_xor_sync(FULLM, pt[k], 2);
    }
    float lg = (bq == 0) ? ph[0] : (bq == 1) ? ph[1] : (bq == 2) ? ph[2] : ph[3];
    float ts = (bq == 0) ? pt[0] : (bq == 1) ? pt[1] : (bq == 2) ? pt[2] : pt[3];

    // softmax over the 64 slots of this hop (warp pair)
    float mx = lg;
    #pragma unroll
    for (int o = 16; o; o >>= 1) mx = fmaxf(mx, __shfl_xor_sync(FULLM, mx, o));
    if (lane == 0) s_wmax[w] = mx;
    __syncthreads();
    const int pw = w & 2;
    float gmax = fmaxf(s_wmax[pw], s_wmax[pw + 1]);
    float ex = __expf(lg - gmax);
    float sm = ex;
    #pragma unroll
    for (int o = 16; o; o >>= 1) sm += __shfl_xor_sync(FULLM, sm, o);
    if (lane == 0) s_wsum[w] = sm;
    __syncthreads();
    float pi = ex / (s_wsum[pw] + s_wsum[pw + 1]);

    // block reduce of pi*(tail·item)
    float p = pi * ts;
    #pragma unroll
    for (int o = 16; o; o >>= 1) p += __shfl_xor_sync(FULLM, p, o);
    if (lane == 0) s_red[w] = p;
    __syncthreads();

    if (tid == 0) {
        float tot = s_red[0] + s_red[1] + s_red[2] + s_red[3];
        out[b] = 1.f / (1.f + __expf(-tot));
    }
}

extern "C" void kernel_launch(void* const* d_in, const int* in_sizes, int n_in,
                              void* d_out, int out_size) {
    q_precompute_kernel<<<BB / 4, 128>>>(
        (const int*)d_in[0],
        (const float*)d_in[4],
        (const float*)d_in[5]);
    ripple_kernel<<<BB, 128>>>(
        (const int*)d_in[0],     // items     [B]
        (const int*)d_in[1],     // heads     [H,B,M]
        (const int*)d_in[2],     // relations [H,B,M]
        (const int*)d_in[3],     // tails     [H,B,M]
        (const float*)d_in[4],   // ent_emb   [N_ENT, D]
        (float*)d_out);          // predicts  [B]
}